// round 9
// baseline (speedup 1.0000x reference)
#include <cuda_runtime.h>
#include <cstdint>

// Z gate (DIM=2) on qudits (0,5,10) of L=14: diagonal phase = parity sign flip.
// sign[n] = (-1)^(bit13(n) ^ bit8(n) ^ bit3(n)); out = [2,N,B] {±xr, ±xi}.
//
// FINAL: pure 512 MiB stream at the mixed-RW HBM3e wall (~6.42 TB/s achieved,
// 80% of spec — confirmed invariant across MLP depth, occupancy, grid shape,
// access width, and cache policy over 5 prior rounds). 256-bit vector
// accesses (LDG.E.256/STG.E.256), non-coherent evict-first loads, default
// stores (L2 buffers write bursts).

static constexpr int N_ROWS = 16384;
static constexpr int B_COLS = 2048;
static constexpr long long TOTAL = (long long)N_ROWS * B_COLS;   // 33,554,432 floats
static constexpr int TOTAL8 = (int)(TOTAL / 8);                  // 4,194,304 32B-vecs

struct v8 { uint32_t r[8]; };

__device__ __forceinline__ v8 ldnc8(const uint32_t* p) {
    v8 v;
    asm volatile("ld.global.nc.cs.v8.b32 {%0,%1,%2,%3,%4,%5,%6,%7}, [%8];"
                 : "=r"(v.r[0]), "=r"(v.r[1]), "=r"(v.r[2]), "=r"(v.r[3]),
                   "=r"(v.r[4]), "=r"(v.r[5]), "=r"(v.r[6]), "=r"(v.r[7])
                 : "l"(p));
    return v;
}
__device__ __forceinline__ void st8(uint32_t* p, const v8& v) {
    asm volatile("st.global.v8.b32 [%0], {%1,%2,%3,%4,%5,%6,%7,%8};"
                 :: "l"(p),
                    "r"(v.r[0]), "r"(v.r[1]), "r"(v.r[2]), "r"(v.r[3]),
                    "r"(v.r[4]), "r"(v.r[5]), "r"(v.r[6]), "r"(v.r[7])
                 : "memory");
}

__global__ void __launch_bounds__(256)
z_phase_kernel(const uint32_t* __restrict__ xr,
               const uint32_t* __restrict__ xi,
               uint32_t* __restrict__ out_r,
               uint32_t* __restrict__ out_i)
{
    int idx = blockIdx.x * blockDim.x + threadIdx.x;   // 8-float vector index
    if (idx >= TOTAL8) return;

    // element index = idx*8; row n = (idx*8) >> 11 = idx >> 8 (B=2048 floats/row)
    unsigned n = ((unsigned)idx) >> 8;
    unsigned mask = (((n >> 13) ^ (n >> 8) ^ (n >> 3)) & 1u) << 31;

    v8 a = ldnc8(xr + (size_t)idx * 8);
    v8 b = ldnc8(xi + (size_t)idx * 8);

#pragma unroll
    for (int k = 0; k < 8; k++) { a.r[k] ^= mask; b.r[k] ^= mask; }

    st8(out_r + (size_t)idx * 8, a);
    st8(out_i + (size_t)idx * 8, b);
}

extern "C" void kernel_launch(void* const* d_in, const int* in_sizes, int n_in,
                              void* d_out, int out_size)
{
    const uint32_t* xr = (const uint32_t*)d_in[0];
    const uint32_t* xi = (const uint32_t*)d_in[1];
    uint32_t* out = (uint32_t*)d_out;
    uint32_t* out_r = out;                       // [N, B] real part
    uint32_t* out_i = out + TOTAL;               // [N, B] imag part

    const int threads = 256;
    const int blocks = TOTAL8 / threads;         // 16384, exact (no tail)
    z_phase_kernel<<<blocks, threads>>>(xr, xi, out_r, out_i);
}